// round 14
// baseline (speedup 1.0000x reference)
#include <cuda_runtime.h>
#include <cuda_fp16.h>
#include <cstdint>

// out[b, :] = (1/K) * sum_k table[idx[b,k], :],  V=200000 D=128 B=50000 K=32.
//
// R13 analysis: gather is pinned at the chip LTS cap (~6300 B/cyc); convert is
// pinned at HBM. Sequential floor = 45.5us. Break it by D-column pipelining:
//   L1: convert cols 0-63                       (HBM-bound)
//   L2: gather cols 0-63  ||  convert cols 64-127 (fused grid, complementary)
//   L3: gather cols 64-127                      (LTS-bound, table L2-hot)

static constexpr long long MAX_VD4 = 6400000;   // 200000*128/4 uint2 slots
__device__ uint2 g_tab16[MAX_VD4];              // fp16 table: 51.2 MB scratch

__device__ __forceinline__ unsigned long long make_policy_el() {
    unsigned long long pol;
    asm("createpolicy.fractional.L2::evict_last.b64 %0, 1.0;" : "=l"(pol));
    return pol;
}

__device__ __forceinline__ uint2 ldg64_pol(const char* p, unsigned long long pol) {
    uint2 v;
    asm volatile("ld.global.nc.L2::cache_hint.v2.b32 {%0,%1}, [%2], %3;"
                 : "=r"(v.x), "=r"(v.y) : "l"(p), "l"(pol));
    return v;
}

// ---- convert body: thread t converts 8 f32 (32B) of half h to 16B fp16 ----
__device__ __forceinline__ void convert_body(const float4* __restrict__ tabf32,
                                             int t, int h, int nthr)
{
    if (t >= nthr) return;
    const unsigned long long pol = make_policy_el();
    const int row = t >> 3;
    const int seg = t & 7;
    const int f4i = row * 32 + h * 16 + seg * 2;    // float4 index into f32 table
    float4 a = __ldcs(&tabf32[f4i]);
    float4 b = __ldcs(&tabf32[f4i + 1]);
    __half2 h0 = __floats2half2_rn(a.x, a.y);
    __half2 h1 = __floats2half2_rn(a.z, a.w);
    __half2 h2 = __floats2half2_rn(b.x, b.y);
    __half2 h3 = __floats2half2_rn(b.z, b.w);
    unsigned u0 = *reinterpret_cast<unsigned*>(&h0);
    unsigned u1 = *reinterpret_cast<unsigned*>(&h1);
    unsigned u2 = *reinterpret_cast<unsigned*>(&h2);
    unsigned u3 = *reinterpret_cast<unsigned*>(&h3);
    // fp16 dst: same uint2 index layout (row*32 + h*16 + seg*2), 16B store
    asm volatile("st.global.L2::cache_hint.v4.b32 [%0], {%1,%2,%3,%4}, %5;"
                 :: "l"(&g_tab16[f4i]), "r"(u0), "r"(u1), "r"(u2), "r"(u3),
                    "l"(pol));
}

// ---- gather body: warp w accumulates half h (64 f32 cols) of output row w --
__device__ __forceinline__ void gather_body(const int* __restrict__ idx,
                                            char* __restrict__ outb,
                                            int w, int lane, int h, int B)
{
    if (w >= B) return;
    const unsigned long long pol = make_policy_el();
    const char* tab = (const char*)g_tab16;

    int my_idx = __ldcs(&idx[(long long)w * 32 + lane]);

    const int grp = lane >> 4;                  // 0: rows k, 1: rows k+1
    const int sub = lane & 15;                  // 8B chunk within 128B half-row
    const unsigned base = (unsigned)h * 128u + (unsigned)sub * 8u;

    float a0 = 0.f, a1 = 0.f, a2 = 0.f, a3 = 0.f;

#pragma unroll 2
    for (int k = 0; k < 32; k += 4) {
        int n0 = __shfl_sync(0xffffffffu, my_idx, k + grp);        // rows k/k+1
        uint2 v0 = ldg64_pol(tab + (unsigned)n0 * 256u + base, pol);
        int n1 = __shfl_sync(0xffffffffu, my_idx, k + 2 + grp);    // rows k+2/k+3
        uint2 v1 = ldg64_pol(tab + (unsigned)n1 * 256u + base, pol);

        __half2 s0 = __hadd2(*reinterpret_cast<__half2*>(&v0.x),
                             *reinterpret_cast<__half2*>(&v1.x));
        __half2 s1 = __hadd2(*reinterpret_cast<__half2*>(&v0.y),
                             *reinterpret_cast<__half2*>(&v1.y));
        float2 f0 = __half22float2(s0);
        float2 f1 = __half22float2(s1);
        a0 += f0.x; a1 += f0.y; a2 += f1.x; a3 += f1.y;
    }

    // combine rows-even half with rows-odd half (same sub on both sides)
    a0 += __shfl_xor_sync(0xffffffffu, a0, 16);
    a1 += __shfl_xor_sync(0xffffffffu, a1, 16);
    a2 += __shfl_xor_sync(0xffffffffu, a2, 16);
    a3 += __shfl_xor_sync(0xffffffffu, a3, 16);

    if (grp == 0) {
        const float inv = 1.0f / 32.0f;
        a0 *= inv; a1 *= inv; a2 *= inv; a3 *= inv;
        // f32 out cols h*64 + 4*sub .. +4 -> byte ofs w*512 + h*256 + sub*16
        char* p = outb + (long long)w * 512 + h * 256 + sub * 16;
        asm volatile("st.global.cs.v4.f32 [%0], {%1,%2,%3,%4};"
                     :: "l"(p), "f"(a0), "f"(a1), "f"(a2), "f"(a3));
    }
}

// ---------------- launch 1: convert half 0 ----------------
__global__ __launch_bounds__(128) void convert_lo(
    const float4* __restrict__ tabf32, int nthr)
{
    convert_body(tabf32, blockIdx.x * 128 + threadIdx.x, 0, nthr);
}

// ------- launch 2: fused  even CTAs gather half 0 | odd CTAs convert half 1 --
__global__ __launch_bounds__(128) void stage2_fused(
    const float4* __restrict__ tabf32,
    const int* __restrict__ idx,
    char* __restrict__ outb,
    int B, int nthr)
{
    const int bid = blockIdx.x;
    if (bid & 1) {
        convert_body(tabf32, (bid >> 1) * 128 + threadIdx.x, 1, nthr);
    } else {
        const int w = (bid >> 1) * 4 + (threadIdx.x >> 5);
        gather_body(idx, outb, w, threadIdx.x & 31, 0, B);
    }
}

// ---------------- launch 3: gather half 1 ----------------
__global__ __launch_bounds__(128) void gather_hi(
    const int* __restrict__ idx,
    char* __restrict__ outb,
    int B)
{
    const int w = blockIdx.x * 4 + (threadIdx.x >> 5);
    gather_body(idx, outb, w, threadIdx.x & 31, 1, B);
}

// ---------------- fallback: f32 path (K != 32 or odd shapes) --------
__global__ __launch_bounds__(256) void gather_mean_generic(
    const float4* __restrict__ table,
    const int* __restrict__ idx,
    float4* __restrict__ out,
    int B, int K)
{
    const int warp = (blockIdx.x * blockDim.x + threadIdx.x) >> 5;
    const int lane = threadIdx.x & 31;
    if (warp >= B) return;

    const int* row_idx = idx + (long long)warp * K;

    float4 acc = make_float4(0.f, 0.f, 0.f, 0.f);
    int k = 0;
    for (; k + 8 <= K; k += 8) {
        float4 v[8];
#pragma unroll
        for (int j = 0; j < 8; ++j) {
            int n = __ldg(&row_idx[k + j]);
            v[j] = __ldg(&table[(long long)n * 32 + lane]);
        }
#pragma unroll
        for (int j = 0; j < 8; ++j) {
            acc.x += v[j].x; acc.y += v[j].y;
            acc.z += v[j].z; acc.w += v[j].w;
        }
    }
    for (; k < K; ++k) {
        int n = row_idx[k];
        float4 v = __ldg(&table[(long long)n * 32 + lane]);
        acc.x += v.x; acc.y += v.y; acc.z += v.z; acc.w += v.w;
    }

    const float inv = 1.0f / (float)K;
    acc.x *= inv; acc.y *= inv; acc.z *= inv; acc.w *= inv;
    out[(long long)warp * 32 + lane] = acc;
}

extern "C" void kernel_launch(void* const* d_in, const int* in_sizes, int n_in,
                              void* d_out, int out_size)
{
    const int B = out_size / 128;                   // rows of output (D=128)
    const int K = (B > 0) ? (in_sizes[1] / B) : 0;
    const long long VD = (long long)in_sizes[0];    // table element count

    if (K == 32 && (VD & 127) == 0 && VD / 4 <= MAX_VD4) {
        const float4* tabf32 = (const float4*)d_in[0];
        const int*    idx    = (const int*)d_in[1];
        char*         outb   = (char*)d_out;

        const int nthr = (int)(VD / 16);            // threads per convert half
        const int cb = (nthr + 127) / 128;          // convert blocks per half
        const int gb = (B + 3) / 4;                 // gather blocks per half
        const int s2 = 2 * (cb > gb ? cb : gb);     // fused interleaved grid

        convert_lo<<<cb, 128>>>(tabf32, nthr);
        stage2_fused<<<s2, 128>>>(tabf32, idx, outb, B, nthr);
        gather_hi<<<gb, 128>>>(idx, outb, B);
    } else {
        const float4* table = (const float4*)d_in[0];
        const int*    idx   = (const int*)d_in[1];
        float4*       out   = (float4*)d_out;
        const int blocks = (B + 7) / 8;
        gather_mean_generic<<<blocks, 256>>>(table, idx, out, B, K);
    }
}

// round 15
// speedup vs baseline: 1.1327x; 1.1327x over previous
#include <cuda_runtime.h>
#include <cuda_fp16.h>
#include <cstdint>

// out[b, :] = (1/K) * sum_k table[idx[b,k], :],  V=200000 D=128 B=50000 K=32.
//
// Pass 1: f32 table -> fp16 scratch (51.2MB; evict_last stores keep it
//         L2-resident). Streaming, ~8.2 TB/s (HBM floor).
// Pass 2: fp16 gather (R11 structure: warp/row, LDG.64/lane, batch-4, full
//         unroll, regs<=32). New: depth-2 fp16 pre-reduction — 4 rows combined
//         by a 3-level __hadd2 tree before one cvt+f32-add set. ~19% fewer
//         issue slots per k. rel_err budget ~3.4e-4 (<1e-3).

static constexpr long long MAX_VD4 = 6400000;   // 200000*128/4 uint2 slots
__device__ uint2 g_tab16[MAX_VD4];              // fp16 table: 51.2 MB scratch

__device__ __forceinline__ unsigned long long make_policy_el() {
    unsigned long long pol;
    asm("createpolicy.fractional.L2::evict_last.b64 %0, 1.0;" : "=l"(pol));
    return pol;
}

// ---------------- pass 1: f32 -> f16 convert (streaming) ----------------
__global__ __launch_bounds__(256) void convert_f32_to_f16(
    const float4* __restrict__ in, long long n8)   // n8 = pairs of float4
{
    long long i = (long long)blockIdx.x * blockDim.x + threadIdx.x;
    if (i >= n8) return;
    const unsigned long long pol = make_policy_el();

    float4 a = __ldcs(&in[2 * i]);
    float4 b = __ldcs(&in[2 * i + 1]);
    __half2 h0 = __floats2half2_rn(a.x, a.y);
    __half2 h1 = __floats2half2_rn(a.z, a.w);
    __half2 h2 = __floats2half2_rn(b.x, b.y);
    __half2 h3 = __floats2half2_rn(b.z, b.w);
    unsigned u0 = *reinterpret_cast<unsigned*>(&h0);
    unsigned u1 = *reinterpret_cast<unsigned*>(&h1);
    unsigned u2 = *reinterpret_cast<unsigned*>(&h2);
    unsigned u3 = *reinterpret_cast<unsigned*>(&h3);
    asm volatile("st.global.L2::cache_hint.v4.b32 [%0], {%1,%2,%3,%4}, %5;"
                 :: "l"(&g_tab16[2 * i]), "r"(u0), "r"(u1), "r"(u2), "r"(u3),
                    "l"(pol));
}

// ---------------- pass 2: fp16 gather ----------------
__device__ __forceinline__ uint2 ldg64_pol(const char* p, unsigned long long pol) {
    uint2 v;
    asm volatile("ld.global.nc.L2::cache_hint.v2.b32 {%0,%1}, [%2], %3;"
                 : "=r"(v.x), "=r"(v.y) : "l"(p), "l"(pol));
    return v;
}

__global__ __launch_bounds__(128) void gather_mean_f16_k32(
    const int* __restrict__ idx,
    float4* __restrict__ out,
    int B)
{
    const int warp = (blockIdx.x * blockDim.x + threadIdx.x) >> 5;
    const int lane = threadIdx.x & 31;
    if (warp >= B) return;

    const unsigned long long pol = make_policy_el();
    const char* tab = (const char*)g_tab16;     // byte base; offsets fit in u32

    // coalesced 128B streaming load of this row's 32 indices
    int my_idx = __ldcs(&idx[(long long)warp * 32 + lane]);

    const unsigned laneOfs = (unsigned)lane * 8u;

    float ax = 0.f, ay = 0.f, az = 0.f, aw = 0.f;

#pragma unroll
    for (int kb = 0; kb < 32; kb += 4) {
        uint2 v[4];
#pragma unroll
        for (int j = 0; j < 4; ++j) {
            int n = __shfl_sync(0xffffffffu, my_idx, kb + j);
            unsigned ofs = (unsigned)n * 256u + laneOfs;   // fp16 row = 256B
            v[j] = ldg64_pol(tab + ofs, pol);
        }
        // depth-2 fp16 pre-reduction: combine 4 rows before conversion
        __half2 p0 = __hadd2(*reinterpret_cast<__half2*>(&v[0].x),
                             *reinterpret_cast<__half2*>(&v[1].x));
        __half2 q0 = __hadd2(*reinterpret_cast<__half2*>(&v[2].x),
                             *reinterpret_cast<__half2*>(&v[3].x));
        __half2 p1 = __hadd2(*reinterpret_cast<__half2*>(&v[0].y),
                             *reinterpret_cast<__half2*>(&v[1].y));
        __half2 q1 = __hadd2(*reinterpret_cast<__half2*>(&v[2].y),
                             *reinterpret_cast<__half2*>(&v[3].y));
        __half2 s0 = __hadd2(p0, q0);
        __half2 s1 = __hadd2(p1, q1);
        float2 f0 = __half22float2(s0);
        float2 f1 = __half22float2(s1);
        ax += f0.x; ay += f0.y;
        az += f1.x; aw += f1.y;
    }

    const float inv = 1.0f / 32.0f;
    float4 r;
    r.x = ax * inv; r.y = ay * inv; r.z = az * inv; r.w = aw * inv;
    __stcs(&out[(long long)warp * 32 + lane], r);
}

// ---------------- fallback: f32 path (K != 32 or oversized table) --------
__global__ __launch_bounds__(256) void gather_mean_generic(
    const float4* __restrict__ table,
    const int* __restrict__ idx,
    float4* __restrict__ out,
    int B, int K)
{
    const int warp = (blockIdx.x * blockDim.x + threadIdx.x) >> 5;
    const int lane = threadIdx.x & 31;
    if (warp >= B) return;

    const int* row_idx = idx + (long long)warp * K;

    float4 acc = make_float4(0.f, 0.f, 0.f, 0.f);
    int k = 0;
    for (; k + 8 <= K; k += 8) {
        float4 v[8];
#pragma unroll
        for (int j = 0; j < 8; ++j) {
            int n = __ldg(&row_idx[k + j]);
            v[j] = __ldg(&table[(long long)n * 32 + lane]);
        }
#pragma unroll
        for (int j = 0; j < 8; ++j) {
            acc.x += v[j].x; acc.y += v[j].y;
            acc.z += v[j].z; acc.w += v[j].w;
        }
    }
    for (; k < K; ++k) {
        int n = row_idx[k];
        float4 v = __ldg(&table[(long long)n * 32 + lane]);
        acc.x += v.x; acc.y += v.y; acc.z += v.z; acc.w += v.w;
    }

    const float inv = 1.0f / (float)K;
    acc.x *= inv; acc.y *= inv; acc.z *= inv; acc.w *= inv;
    out[(long long)warp * 32 + lane] = acc;
}

extern "C" void kernel_launch(void* const* d_in, const int* in_sizes, int n_in,
                              void* d_out, int out_size)
{
    const int B = out_size / 128;                   // rows of output
    const int K = (B > 0) ? (in_sizes[1] / B) : 0;
    const long long VD = (long long)in_sizes[0];    // table element count

    if (K == 32 && VD % 8 == 0 && VD / 4 <= MAX_VD4 && (VD & 127) == 0) {
        const float4* table = (const float4*)d_in[0];
        const int*    idx   = (const int*)d_in[1];
        float4*       out   = (float4*)d_out;

        const long long n8 = VD / 8;                // 2 float4 per thread
        const int cblocks = (int)((n8 + 255) / 256);
        convert_f32_to_f16<<<cblocks, 256>>>(table, n8);

        const int gblocks = (B + 3) / 4;            // 4 warps/block, 1 row/warp
        gather_mean_f16_k32<<<gblocks, 128>>>(idx, out, B);
    } else {
        const float4* table = (const float4*)d_in[0];
        const int*    idx   = (const int*)d_in[1];
        float4*       out   = (float4*)d_out;
        const int blocks = (B + 7) / 8;
        gather_mean_generic<<<blocks, 256>>>(table, idx, out, B, K);
    }
}